// round 7
// baseline (speedup 1.0000x reference)
#include <cuda_runtime.h>

// Fixed shapes: B=8, H=W=64, C=256, red=64, G=16, GC=16, kk=9, E=144
#define XS  260   // halo row stride (floats)
#define TS  68    // t row stride (floats)

// smem floats: xs[100*260]=26000 | W1s[256*64]=16384 | W2t[144*64]=9216 | ts[64*68]=4352
#define SM_FLOATS (100*XS + 256*64 + 144*64 + 64*TS)   // 55952 -> 223808 B

typedef unsigned long long ull;

__device__ __forceinline__ ull pack2(float lo, float hi) {
    ull r;
    asm("mov.b64 %0, {%1, %2};" : "=l"(r) : "f"(lo), "f"(hi));
    return r;
}
__device__ __forceinline__ void unpack2(ull v, float& lo, float& hi) {
    asm("mov.b64 {%0, %1}, %2;" : "=f"(lo), "=f"(hi) : "l"(v));
}
__device__ __forceinline__ void ffma2(ull& d, ull a, ull b) {
    asm("fma.rn.f32x2 %0, %1, %2, %0;" : "+l"(d) : "l"(a), "l"(b));
}

__global__ void __launch_bounds__(512, 1) invo_fused(
    const float* __restrict__ x,
    const float* __restrict__ W1, const float* __restrict__ b1,
    const float* __restrict__ W2, const float* __restrict__ b2,
    float* __restrict__ out)
{
    extern __shared__ float sm[];
    float* xs  = sm;                 // [100][XS]  10x10 halo, 256 ch
    float* W1s = sm + 100 * XS;      // [256][64]
    float* W2t = W1s + 256 * 64;     // [144][64]  transposed: W2t[e*64+k] = W2[k][e]
    float* ts  = W2t + 144 * 64;     // [64][TS]

    const int tid = threadIdx.x;
    const int blk = blockIdx.x;
    const int b   = blk >> 6;
    const int ty  = (blk >> 3) & 7;
    const int tw  = blk & 7;
    const int h0  = ty * 8, w0 = tw * 8;

    // ---- cooperative loads ----
    {   // W1 [256][64] : 4096 float4
        const float4* src = (const float4*)W1;
        float4* dst = (float4*)W1s;
        for (int i = tid; i < 4096; i += 512) dst[i] = src[i];
    }
    {   // W2 [64][144] -> W2t [144][64]
        for (int i = tid; i < 9216; i += 512) {
            int e = i >> 6, k = i & 63;
            W2t[i] = W2[k * 144 + e];
        }
    }
    {   // halo: 100 pixel slots x 64 float4, zero-pad OOB
        for (int i = tid; i < 6400; i += 512) {
            int slot = i >> 6, c4 = i & 63;
            int py = slot / 10, px = slot - py * 10;
            int gh = h0 + py - 1, gw = w0 + px - 1;
            float4 v = make_float4(0.f, 0.f, 0.f, 0.f);
            if ((unsigned)gh < 64u && (unsigned)gw < 64u)
                v = *(const float4*)(x + ((size_t)((b * 64 + gh) * 64 + gw)) * 256 + c4 * 4);
            *(float4*)&xs[slot * XS + c4 * 4] = v;
        }
    }
    __syncthreads();

    // ---- Stage A: t[64][64] = x_tile @ W1 + b1 ----
    // thread: 1 pixel (tid>>3), 8 cols {4tx..4tx+3, 32+4tx..32+4tx+3} (conflict-free W loads)
    {
        const int px = tid >> 3, tx = tid & 7;
        const int py = px >> 3, pxx = px & 7;
        const float* arow = &xs[((py + 1) * 10 + pxx + 1) * XS];
        const int cA = 4 * tx, cB = 32 + 4 * tx;

        ull accA0 = pack2(b1[cA],     b1[cA + 1]);
        ull accA1 = pack2(b1[cA + 2], b1[cA + 3]);
        ull accB0 = pack2(b1[cB],     b1[cB + 1]);
        ull accB1 = pack2(b1[cB + 2], b1[cB + 3]);

        #pragma unroll 2
        for (int k = 0; k < 256; k += 4) {
            float4 a4 = *(const float4*)&arow[k];
            #pragma unroll
            for (int kk = 0; kk < 4; kk++) {
                float a = (&a4.x)[kk];
                ull A = pack2(a, a);
                ulonglong2 wa = *(const ulonglong2*)&W1s[(k + kk) * 64 + cA];
                ulonglong2 wb = *(const ulonglong2*)&W1s[(k + kk) * 64 + cB];
                ffma2(accA0, A, wa.x); ffma2(accA1, A, wa.y);
                ffma2(accB0, A, wb.x); ffma2(accB1, A, wb.y);
            }
        }
        *(ull*)&ts[px * TS + cA]     = accA0;
        *(ull*)&ts[px * TS + cA + 2] = accA1;
        *(ull*)&ts[px * TS + cB]     = accB0;
        *(ull*)&ts[px * TS + cB + 2] = accB1;
    }
    __syncthreads();

    // ---- Stage B: wgt kept in registers. thread = (px {lane, lane+32}) x (g = warp) ----
    const int lane = tid & 31;
    const int g    = tid >> 5;           // 0..15, uniform per warp

    ull  acc[2][4];                      // [px][col-pair j]
    float acc8[2];
    {
        const float* bb = b2 + g * 9;
        ull b01 = pack2(bb[0], bb[1]);
        ull b23 = pack2(bb[2], bb[3]);
        ull b45 = pack2(bb[4], bb[5]);
        ull b67 = pack2(bb[6], bb[7]);
        float b8 = bb[8];
        #pragma unroll
        for (int i = 0; i < 2; i++) {
            acc[i][0] = b01; acc[i][1] = b23; acc[i][2] = b45; acc[i][3] = b67;
            acc8[i] = b8;
        }
    }
    {
        const float* t0r = &ts[lane * TS];
        const float* t1r = &ts[(lane + 32) * TS];
        const float* wb  = &W2t[g * 9 * 64];

        for (int k = 0; k < 64; k += 4) {
            float4 t0 = *(const float4*)&t0r[k];
            float4 t1 = *(const float4*)&t1r[k];
            float4 w[9];
            #pragma unroll
            for (int j = 0; j < 9; j++) w[j] = *(const float4*)&wb[j * 64 + k];  // uniform

            #pragma unroll
            for (int kk = 0; kk < 4; kk++) {
                ull W01 = pack2((&w[0].x)[kk], (&w[1].x)[kk]);
                ull W23 = pack2((&w[2].x)[kk], (&w[3].x)[kk]);
                ull W45 = pack2((&w[4].x)[kk], (&w[5].x)[kk]);
                ull W67 = pack2((&w[6].x)[kk], (&w[7].x)[kk]);
                float w8v = (&w[8].x)[kk];

                float a0 = (&t0.x)[kk];
                ull A0 = pack2(a0, a0);
                ffma2(acc[0][0], A0, W01); ffma2(acc[0][1], A0, W23);
                ffma2(acc[0][2], A0, W45); ffma2(acc[0][3], A0, W67);
                acc8[0] = fmaf(a0, w8v, acc8[0]);

                float a1 = (&t1.x)[kk];
                ull A1 = pack2(a1, a1);
                ffma2(acc[1][0], A1, W01); ffma2(acc[1][1], A1, W23);
                ffma2(acc[1][2], A1, W45); ffma2(acc[1][3], A1, W67);
                acc8[1] = fmaf(a1, w8v, acc8[1]);
            }
        }
    }
    // no sync: only xs is read below, unchanged since first sync

    // ---- Involution ----
    float wr0[9], wr1[9];
    unpack2(acc[0][0], wr0[0], wr0[1]); unpack2(acc[0][1], wr0[2], wr0[3]);
    unpack2(acc[0][2], wr0[4], wr0[5]); unpack2(acc[0][3], wr0[6], wr0[7]);
    wr0[8] = acc8[0];
    unpack2(acc[1][0], wr1[0], wr1[1]); unpack2(acc[1][1], wr1[2], wr1[3]);
    unpack2(acc[1][2], wr1[4], wr1[5]); unpack2(acc[1][3], wr1[6], wr1[7]);
    wr1[8] = acc8[1];

    const int py0 = lane >> 3, pxx = lane & 7;
    // FIX (R6 bug): window top-left for pixel (py0,pxx) is halo slot (py0, pxx),
    // i.e. base WITHOUT the +1 center offset; off then adds (ni*10+nj), ni,nj in 0..2.
    const int base0 = (py0 * 10 + pxx) * XS;
    const int base1 = base0 + 40 * XS;                       // pixel row py0+4
    float* orow0 = out + ((size_t)((b * 64 + h0 + py0) * 64 + w0 + pxx)) * 256 + g * 16;
    float* orow1 = orow0 + (size_t)4 * 64 * 256;

    #pragma unroll
    for (int gcc = 0; gcc < 4; gcc++) {
        float o0[4] = {0.f, 0.f, 0.f, 0.f};
        float o1[4] = {0.f, 0.f, 0.f, 0.f};
        #pragma unroll
        for (int u = 0; u < 9; u++) {
            int f  = g * 144 + gcc * 36 + 4 * u;
            int n  = f >> 8;          // neighbor, constant across the float4
            int ch = f & 255;
            int ni = n / 3, nj = n - ni * 3;
            int off = (ni * 10 + nj) * XS + ch;
            float4 v0 = *(const float4*)&xs[base0 + off];
            float4 v1 = *(const float4*)&xs[base1 + off];
            const int i0 = 4 * u;
            o0[(i0 + 0) / 9] = fmaf(wr0[(i0 + 0) % 9], v0.x, o0[(i0 + 0) / 9]);
            o0[(i0 + 1) / 9] = fmaf(wr0[(i0 + 1) % 9], v0.y, o0[(i0 + 1) / 9]);
            o0[(i0 + 2) / 9] = fmaf(wr0[(i0 + 2) % 9], v0.z, o0[(i0 + 2) / 9]);
            o0[(i0 + 3) / 9] = fmaf(wr0[(i0 + 3) % 9], v0.w, o0[(i0 + 3) / 9]);
            o1[(i0 + 0) / 9] = fmaf(wr1[(i0 + 0) % 9], v1.x, o1[(i0 + 0) / 9]);
            o1[(i0 + 1) / 9] = fmaf(wr1[(i0 + 1) % 9], v1.y, o1[(i0 + 1) / 9]);
            o1[(i0 + 2) / 9] = fmaf(wr1[(i0 + 2) % 9], v1.z, o1[(i0 + 2) / 9]);
            o1[(i0 + 3) / 9] = fmaf(wr1[(i0 + 3) % 9], v1.w, o1[(i0 + 3) / 9]);
        }
        *(float4*)&orow0[gcc * 4] = make_float4(o0[0], o0[1], o0[2], o0[3]);
        *(float4*)&orow1[gcc * 4] = make_float4(o1[0], o1[1], o1[2], o1[3]);
    }
}

extern "C" void kernel_launch(void* const* d_in, const int* in_sizes, int n_in,
                              void* d_out, int out_size) {
    const float* x  = (const float*)d_in[0];
    const float* W1 = (const float*)d_in[1];
    const float* b1 = (const float*)d_in[2];
    const float* W2 = (const float*)d_in[3];
    const float* b2 = (const float*)d_in[4];
    float* out = (float*)d_out;

    const int SM = SM_FLOATS * 4;   // 223808 B
    cudaFuncSetAttribute(invo_fused, cudaFuncAttributeMaxDynamicSharedMemorySize, SM);
    invo_fused<<<512, 512, SM>>>(x, W1, b1, W2, b2, out);
}

// round 8
// speedup vs baseline: 1.0265x; 1.0265x over previous
#include <cuda_runtime.h>
#include <cstdint>

// Fixed shapes: B=8, H=W=64, C=256, red=64, G=16, GC=16, kk=9, E=144, NPIX=32768
#define NPIX 32768

// wgt scratch in [g][pix][9] layout for coalesced K2 reads: 16*32768*9 floats = 18.9MB
__device__ float g_wgt[(size_t)16 * NPIX * 9];

typedef unsigned long long ull;

__device__ __forceinline__ ull pack2(float lo, float hi) {
    ull r; asm("mov.b64 %0, {%1, %2};" : "=l"(r) : "f"(lo), "f"(hi)); return r;
}
__device__ __forceinline__ void unpack2(ull v, float& lo, float& hi) {
    asm("mov.b64 {%0, %1}, %2;" : "=f"(lo), "=f"(hi) : "l"(v));
}
__device__ __forceinline__ void ffma2(ull& d, ull a, ull b) {
    asm("fma.rn.f32x2 %0, %1, %2, %0;" : "+l"(d) : "l"(a), "l"(b));
}
__device__ __forceinline__ unsigned tf32_rna(float a) {
    unsigned r; asm("cvt.rna.tf32.f32 %0, %1;" : "=r"(r) : "f"(a)); return r;
}
__device__ __forceinline__ void mma_tf32(float* c, const unsigned* a, unsigned b0, unsigned b1) {
    asm("mma.sync.aligned.m16n8k8.row.col.f32.tf32.tf32.f32 "
        "{%0,%1,%2,%3}, {%4,%5,%6,%7}, {%8,%9}, {%0,%1,%2,%3};"
        : "+f"(c[0]), "+f"(c[1]), "+f"(c[2]), "+f"(c[3])
        : "r"(a[0]), "r"(a[1]), "r"(a[2]), "r"(a[3]), "r"(b0), "r"(b1));
}

// =====================================================================
// K1: g_wgt = ((x @ W1 + b1) @ W2 + b2), stage A on tensor cores.
// Block = 64 pixels, 256 threads (8 warps). Grid = 512.
// smem (floats):
//   region0 [0..16640):  xs[64][260]   (stage A)   | overlay after mma:
//                        W2t[144][64] at 0..9216, ts[64][68] at 9216..13568
//   region1 [16640..35072): W1s[256][72] (stage A) | overlay: W2tmp[64][148] (9472)
// =====================================================================
#define K1_SM_FLOATS 35072   // 140288 B

__global__ void __launch_bounds__(256, 1) wgt_kernel(
    const float* __restrict__ x,
    const float* __restrict__ W1, const float* __restrict__ b1,
    const float* __restrict__ W2, const float* __restrict__ b2)
{
    extern __shared__ float sm[];
    float* xs    = sm;                // [64][260]
    float* W1s   = sm + 16640;        // [256][72]
    float* W2t   = sm;                // overlay: [144][64]
    float* ts    = sm + 9216;         // overlay: [64][68]
    float* W2tmp = sm + 16640;        // overlay: [64][148]

    const int tid  = threadIdx.x;
    const int pix0 = blockIdx.x * 64;

    // ---- load x tile + W1 ----
    {
        const float4* src = (const float4*)(x + (size_t)pix0 * 256);
        for (int i = tid; i < 4096; i += 256) {
            int r = i >> 6, c4 = i & 63;
            *(float4*)&xs[r * 260 + c4 * 4] = src[i];
        }
    }
    {
        const float4* src = (const float4*)W1;
        for (int i = tid; i < 4096; i += 256) {
            int r = i >> 4, c4 = i & 15;
            *(float4*)&W1s[r * 72 + c4 * 4] = src[i];
        }
    }
    __syncthreads();

    // ---- Stage A: mma.m16n8k8 tf32, hi/lo split (3 mma) ----
    // warp w: mw = w&3 (rows mw*16), nw = w>>2 (cols nw*32, 4 n8-tiles)
    const int w    = tid >> 5, lane = tid & 31;
    const int quad = lane >> 2, tq = lane & 3;
    const int mw   = w & 3,  nw = w >> 2;

    float cfr[4][4];
    #pragma unroll
    for (int nt = 0; nt < 4; nt++)
        #pragma unroll
        for (int j = 0; j < 4; j++) cfr[nt][j] = 0.f;

    {
        const int r0 = mw * 16 + quad;
        for (int ks = 0; ks < 32; ks++) {
            const int kb = ks * 8;
            float af[4];
            af[0] = xs[r0 * 260 + kb + tq];
            af[1] = xs[(r0 + 8) * 260 + kb + tq];
            af[2] = xs[r0 * 260 + kb + tq + 4];
            af[3] = xs[(r0 + 8) * 260 + kb + tq + 4];
            unsigned ahi[4], alo[4];
            #pragma unroll
            for (int j = 0; j < 4; j++) {
                ahi[j] = tf32_rna(af[j]);
                alo[j] = tf32_rna(af[j] - __uint_as_float(ahi[j]));
            }
            #pragma unroll
            for (int nt = 0; nt < 4; nt++) {
                const int n0 = nw * 32 + nt * 8 + quad;
                float b0f = W1s[(kb + tq) * 72 + n0];
                float b1f = W1s[(kb + tq + 4) * 72 + n0];
                unsigned b0h = tf32_rna(b0f);
                unsigned b0l = tf32_rna(b0f - __uint_as_float(b0h));
                unsigned b1h = tf32_rna(b1f);
                unsigned b1l = tf32_rna(b1f - __uint_as_float(b1h));
                mma_tf32(cfr[nt], ahi, b0h, b1h);
                mma_tf32(cfr[nt], ahi, b0l, b1l);
                mma_tf32(cfr[nt], alo, b0h, b1h);
            }
        }
    }
    __syncthreads();   // xs/W1s dead; safe to overlay

    // ---- write ts (+b1) and load W2 (coalesced) ----
    {
        const int r0 = mw * 16 + quad;
        #pragma unroll
        for (int nt = 0; nt < 4; nt++) {
            const int nb = nw * 32 + nt * 8 + 2 * tq;
            float bia0 = b1[nb], bia1 = b1[nb + 1];
            ts[r0 * 68 + nb]           = cfr[nt][0] + bia0;
            ts[r0 * 68 + nb + 1]       = cfr[nt][1] + bia1;
            ts[(r0 + 8) * 68 + nb]     = cfr[nt][2] + bia0;
            ts[(r0 + 8) * 68 + nb + 1] = cfr[nt][3] + bia1;
        }
    }
    {
        const float4* src = (const float4*)W2;
        for (int i = tid; i < 2304; i += 256) {
            int r = i / 36, c4 = i - r * 36;
            *(float4*)&W2tmp[r * 148 + c4 * 4] = src[i];
        }
    }
    __syncthreads();

    // ---- transpose W2tmp[k][e] -> W2t[e][k] ----
    for (int i = tid; i < 9216; i += 256) {
        int e = i >> 6, k = i & 63;
        W2t[e * 64 + k] = W2tmp[k * 148 + e];
    }
    __syncthreads();

    // ---- Stage B: wgt = ts @ W2 + b2, FFMA2, warp-uniform g ----
    // thread: g in {w, w+8}, px in {lane, lane+32}
    ull  acc[2][2][4];
    float acc8[2][2];
    #pragma unroll
    for (int gi = 0; gi < 2; gi++) {
        const int g = w + 8 * gi;
        const float* bb = b2 + g * 9;
        ull b01 = pack2(bb[0], bb[1]), b23 = pack2(bb[2], bb[3]);
        ull b45 = pack2(bb[4], bb[5]), b67 = pack2(bb[6], bb[7]);
        float b8 = bb[8];
        #pragma unroll
        for (int pi = 0; pi < 2; pi++) {
            acc[gi][pi][0] = b01; acc[gi][pi][1] = b23;
            acc[gi][pi][2] = b45; acc[gi][pi][3] = b67;
            acc8[gi][pi] = b8;
        }
    }
    {
        const float* t0r = &ts[lane * 68];
        const float* t1r = &ts[(lane + 32) * 68];
        for (int k = 0; k < 64; k += 4) {
            float4 t0 = *(const float4*)&t0r[k];
            float4 t1 = *(const float4*)&t1r[k];
            #pragma unroll
            for (int gi = 0; gi < 2; gi++) {
                const float* wb = &W2t[(w + 8 * gi) * 9 * 64];
                float4 wv[9];
                #pragma unroll
                for (int j = 0; j < 9; j++) wv[j] = *(const float4*)&wb[j * 64 + k];  // uniform
                #pragma unroll
                for (int kk = 0; kk < 4; kk++) {
                    ull W01 = pack2((&wv[0].x)[kk], (&wv[1].x)[kk]);
                    ull W23 = pack2((&wv[2].x)[kk], (&wv[3].x)[kk]);
                    ull W45 = pack2((&wv[4].x)[kk], (&wv[5].x)[kk]);
                    ull W67 = pack2((&wv[6].x)[kk], (&wv[7].x)[kk]);
                    float w8v = (&wv[8].x)[kk];
                    float a0 = (&t0.x)[kk];
                    ull A0 = pack2(a0, a0);
                    ffma2(acc[gi][0][0], A0, W01); ffma2(acc[gi][0][1], A0, W23);
                    ffma2(acc[gi][0][2], A0, W45); ffma2(acc[gi][0][3], A0, W67);
                    acc8[gi][0] = fmaf(a0, w8v, acc8[gi][0]);
                    float a1 = (&t1.x)[kk];
                    ull A1 = pack2(a1, a1);
                    ffma2(acc[gi][1][0], A1, W01); ffma2(acc[gi][1][1], A1, W23);
                    ffma2(acc[gi][1][2], A1, W45); ffma2(acc[gi][1][3], A1, W67);
                    acc8[gi][1] = fmaf(a1, w8v, acc8[gi][1]);
                }
            }
        }
    }
    // ---- write g_wgt[g][pix][9] (coalesced across lanes) ----
    #pragma unroll
    for (int gi = 0; gi < 2; gi++) {
        const int g = w + 8 * gi;
        #pragma unroll
        for (int pi = 0; pi < 2; pi++) {
            const int px = lane + 32 * pi;
            float wr[9];
            unpack2(acc[gi][pi][0], wr[0], wr[1]); unpack2(acc[gi][pi][1], wr[2], wr[3]);
            unpack2(acc[gi][pi][2], wr[4], wr[5]); unpack2(acc[gi][pi][3], wr[6], wr[7]);
            wr[8] = acc8[gi][pi];
            float* dst = g_wgt + ((size_t)g * NPIX + pix0 + px) * 9;
            #pragma unroll
            for (int j = 0; j < 9; j++) dst[j] = wr[j];
        }
    }
}

// =====================================================================
// K2: involution. Block = 8x8 tile, 256 threads, smem = halo only (104KB)
// -> 2 blocks/SM. wgt read from gmem into registers.
// =====================================================================
#define XS 260
#define K2_SM_FLOATS (100 * XS)   // 104000 B

__global__ void __launch_bounds__(256, 2) invo_kernel(
    const float* __restrict__ x, float* __restrict__ out)
{
    extern __shared__ float sm[];
    float* xs = sm;                  // [100][XS]

    const int tid = threadIdx.x;
    const int blk = blockIdx.x;
    const int b  = blk >> 6;
    const int ty = (blk >> 3) & 7;
    const int tw = blk & 7;
    const int h0 = ty * 8, w0 = tw * 8;

    const int lane = tid & 31, w = tid >> 5;
    const int py0 = lane >> 3, pxx = lane & 7;

    // ---- wgt loads (gmem, independent of smem) issued first ----
    float wr[2][2][9];
    #pragma unroll
    for (int gi = 0; gi < 2; gi++) {
        const int g = w + 8 * gi;
        #pragma unroll
        for (int pi = 0; pi < 2; pi++) {
            const int py = py0 + 4 * pi;
            const int gpix = (b * 64 + h0 + py) * 64 + w0 + pxx;
            const float* src = g_wgt + ((size_t)g * NPIX + gpix) * 9;
            #pragma unroll
            for (int j = 0; j < 9; j++) wr[gi][pi][j] = src[j];
        }
    }

    // ---- halo load: 100 pixel slots x 64 float4, zero-pad OOB ----
    for (int i = tid; i < 6400; i += 256) {
        int slot = i >> 6, c4 = i & 63;
        int py = slot / 10, px = slot - py * 10;
        int gh = h0 + py - 1, gw = w0 + px - 1;
        float4 v = make_float4(0.f, 0.f, 0.f, 0.f);
        if ((unsigned)gh < 64u && (unsigned)gw < 64u)
            v = *(const float4*)(x + ((size_t)((b * 64 + gh) * 64 + gw)) * 256 + c4 * 4);
        *(float4*)&xs[slot * XS + c4 * 4] = v;
    }
    __syncthreads();

    // ---- involution ----
    const int base0 = (py0 * 10 + pxx) * XS;      // window top-left slot (py0, pxx)
    #pragma unroll
    for (int gi = 0; gi < 2; gi++) {
        const int g = w + 8 * gi;
        float* orow0 = out + ((size_t)((b * 64 + h0 + py0) * 64 + w0 + pxx)) * 256 + g * 16;
        float* orow1 = orow0 + (size_t)4 * 64 * 256;
        #pragma unroll
        for (int gcc = 0; gcc < 4; gcc++) {
            float o0[4] = {0.f, 0.f, 0.f, 0.f};
            float o1[4] = {0.f, 0.f, 0.f, 0.f};
            #pragma unroll
            for (int u = 0; u < 9; u++) {
                int f  = g * 144 + gcc * 36 + 4 * u;
                int n  = f >> 8;              // neighbor, constant across the float4
                int ch = f & 255;
                int ni = n / 3, nj = n - ni * 3;
                int off = (ni * 10 + nj) * XS + ch;
                float4 v0 = *(const float4*)&xs[base0 + off];
                float4 v1 = *(const float4*)&xs[base0 + 40 * XS + off];
                const int i0 = 4 * u;
                o0[(i0 + 0) / 9] = fmaf(wr[gi][0][(i0 + 0) % 9], v0.x, o0[(i0 + 0) / 9]);
                o0[(i0 + 1) / 9] = fmaf(wr[gi][0][(i0 + 1) % 9], v0.y, o0[(i0 + 1) / 9]);
                o0[(i0 + 2) / 9] = fmaf(wr[gi][0][(i0 + 2) % 9], v0.z, o0[(i0 + 2) / 9]);
                o0[(i0 + 3) / 9] = fmaf(wr[gi][0][(i0 + 3) % 9], v0.w, o0[(i0 + 3) / 9]);
                o1[(i0 + 0) / 9] = fmaf(wr[gi][1][(i0 + 0) % 9], v1.x, o1[(i0 + 0) / 9]);
                o1[(i0 + 1) / 9] = fmaf(wr[gi][1][(i0 + 1) % 9], v1.y, o1[(i0 + 1) / 9]);
                o1[(i0 + 2) / 9] = fmaf(wr[gi][1][(i0 + 2) % 9], v1.z, o1[(i0 + 2) / 9]);
                o1[(i0 + 3) / 9] = fmaf(wr[gi][1][(i0 + 3) % 9], v1.w, o1[(i0 + 3) / 9]);
            }
            *(float4*)&orow0[gcc * 4] = make_float4(o0[0], o0[1], o0[2], o0[3]);
            *(float4*)&orow1[gcc * 4] = make_float4(o1[0], o1[1], o1[2], o1[3]);
        }
    }
}

extern "C" void kernel_launch(void* const* d_in, const int* in_sizes, int n_in,
                              void* d_out, int out_size) {
    const float* x  = (const float*)d_in[0];
    const float* W1 = (const float*)d_in[1];
    const float* b1 = (const float*)d_in[2];
    const float* W2 = (const float*)d_in[3];
    const float* b2 = (const float*)d_in[4];
    float* out = (float*)d_out;

    const int SM1 = K1_SM_FLOATS * 4;   // 140288 B
    const int SM2 = K2_SM_FLOATS * 4;   // 104000 B
    cudaFuncSetAttribute(wgt_kernel,  cudaFuncAttributeMaxDynamicSharedMemorySize, SM1);
    cudaFuncSetAttribute(invo_kernel, cudaFuncAttributeMaxDynamicSharedMemorySize, SM2);

    wgt_kernel<<<512, 256, SM1>>>(x, W1, b1, W2, b2);
    invo_kernel<<<512, 256, SM2>>>(x, out);
}

// round 9
// speedup vs baseline: 1.2239x; 1.1923x over previous
#include <cuda_runtime.h>
#include <cstdint>

// Fixed shapes: B=8, H=W=64, C=256, red=64, G=16, GC=16, kk=9, E=144, NPIX=32768
#define NPIX 32768

// wgt scratch in [g][pix][9] layout: 16*32768*9 floats = 18.9MB
__device__ float g_wgt[(size_t)16 * NPIX * 9];

typedef unsigned long long ull;

__device__ __forceinline__ ull pack2(float lo, float hi) {
    ull r; asm("mov.b64 %0, {%1, %2};" : "=l"(r) : "f"(lo), "f"(hi)); return r;
}
__device__ __forceinline__ void unpack2(ull v, float& lo, float& hi) {
    asm("mov.b64 {%0, %1}, %2;" : "=f"(lo), "=f"(hi) : "l"(v));
}
__device__ __forceinline__ void ffma2(ull& d, ull a, ull b) {
    asm("fma.rn.f32x2 %0, %1, %2, %0;" : "+l"(d) : "l"(a), "l"(b));
}
__device__ __forceinline__ unsigned tf32_rna(float a) {
    unsigned r; asm("cvt.rna.tf32.f32 %0, %1;" : "=r"(r) : "f"(a)); return r;
}
__device__ __forceinline__ void mma_tf32(float* c, const unsigned* a, unsigned b0, unsigned b1) {
    asm("mma.sync.aligned.m16n8k8.row.col.f32.tf32.tf32.f32 "
        "{%0,%1,%2,%3}, {%4,%5,%6,%7}, {%8,%9}, {%0,%1,%2,%3};"
        : "+f"(c[0]), "+f"(c[1]), "+f"(c[2]), "+f"(c[3])
        : "r"(a[0]), "r"(a[1]), "r"(a[2]), "r"(a[3]), "r"(b0), "r"(b1));
}

// =====================================================================
// K1: g_wgt = ((x @ W1 + b1) @ W2 + b2). 512 threads, 64 pixels, grid 512.
// smem (floats/uints):
//   [0..16640)      xs[64][260]           | overlay: W2t[144][64] @0, ts[64][68] @9216
//   [16640..35072)  W1hi[256][72] (uint)  | overlay: W2tmp[64][148] @16640
//   [35072..53504)  W1lo[256][72] (uint)
// =====================================================================
#define K1_SM_FLOATS 53504   // 214016 B

__global__ void __launch_bounds__(512, 1) wgt_kernel(
    const float* __restrict__ x,
    const float* __restrict__ W1, const float* __restrict__ b1,
    const float* __restrict__ W2, const float* __restrict__ b2)
{
    extern __shared__ float sm[];
    float*    xs    = sm;                          // [64][260]
    unsigned* W1hi  = (unsigned*)(sm + 16640);     // [256][72]
    unsigned* W1lo  = (unsigned*)(sm + 35072);     // [256][72]
    float*    W2t   = sm;                          // overlay [144][64]
    float*    ts    = sm + 9216;                   // overlay [64][68]
    float*    W2tmp = sm + 16640;                  // overlay [64][148]

    const int tid  = threadIdx.x;
    const int pix0 = blockIdx.x * 64;

    // ---- load x tile; load+convert W1 to tf32 hi/lo (once per block) ----
    {
        const float4* src = (const float4*)(x + (size_t)pix0 * 256);
        for (int i = tid; i < 4096; i += 512) {
            int r = i >> 6, c4 = i & 63;
            *(float4*)&xs[r * 260 + c4 * 4] = src[i];
        }
    }
    for (int i = tid; i < 16384; i += 512) {
        int k = i >> 6, c = i & 63;
        float f = W1[i];
        unsigned hi = tf32_rna(f);
        unsigned lo = tf32_rna(f - __uint_as_float(hi));
        W1hi[k * 72 + c] = hi;
        W1lo[k * 72 + c] = lo;
    }
    __syncthreads();

    // ---- Stage A: mma.m16n8k8 tf32, 3-mma hi/lo split ----
    // 16 warps: mw = w&3 (rows mw*16), nw = w>>2 (cols nw*16, 2 n8-tiles)
    const int w    = tid >> 5, lane = tid & 31;
    const int quad = lane >> 2, tq = lane & 3;
    const int mw   = w & 3,  nw = w >> 2;

    float cfr[2][4];
    #pragma unroll
    for (int nt = 0; nt < 2; nt++)
        #pragma unroll
        for (int j = 0; j < 4; j++) cfr[nt][j] = 0.f;

    {
        const int r0 = mw * 16 + quad;
        for (int ks = 0; ks < 32; ks++) {
            const int kb = ks * 8;
            float af[4];
            af[0] = xs[r0 * 260 + kb + tq];
            af[1] = xs[(r0 + 8) * 260 + kb + tq];
            af[2] = xs[r0 * 260 + kb + tq + 4];
            af[3] = xs[(r0 + 8) * 260 + kb + tq + 4];
            unsigned ahi[4], alo[4];
            #pragma unroll
            for (int j = 0; j < 4; j++) {
                ahi[j] = tf32_rna(af[j]);
                alo[j] = tf32_rna(af[j] - __uint_as_float(ahi[j]));
            }
            #pragma unroll
            for (int nt = 0; nt < 2; nt++) {
                const int n0 = nw * 16 + nt * 8 + quad;
                unsigned b0h = W1hi[(kb + tq) * 72 + n0];
                unsigned b1h = W1hi[(kb + tq + 4) * 72 + n0];
                unsigned b0l = W1lo[(kb + tq) * 72 + n0];
                unsigned b1l = W1lo[(kb + tq + 4) * 72 + n0];
                mma_tf32(cfr[nt], ahi, b0h, b1h);
                mma_tf32(cfr[nt], ahi, b0l, b1l);
                mma_tf32(cfr[nt], alo, b0h, b1h);
            }
        }
    }
    __syncthreads();   // xs/W1hi/W1lo dead; overlays live

    // ---- write ts (+b1); load W2 (coalesced) ----
    {
        const int r0 = mw * 16 + quad;
        #pragma unroll
        for (int nt = 0; nt < 2; nt++) {
            const int nb = nw * 16 + nt * 8 + 2 * tq;
            float bia0 = b1[nb], bia1 = b1[nb + 1];
            ts[r0 * 68 + nb]           = cfr[nt][0] + bia0;
            ts[r0 * 68 + nb + 1]       = cfr[nt][1] + bia1;
            ts[(r0 + 8) * 68 + nb]     = cfr[nt][2] + bia0;
            ts[(r0 + 8) * 68 + nb + 1] = cfr[nt][3] + bia1;
        }
    }
    {
        const float4* src = (const float4*)W2;
        for (int i = tid; i < 2304; i += 512) {
            int r = i / 36, c4 = i - r * 36;
            *(float4*)&W2tmp[r * 148 + c4 * 4] = src[i];
        }
    }
    __syncthreads();

    // ---- transpose W2tmp[k][e] -> W2t[e][k] ----
    for (int i = tid; i < 9216; i += 512) {
        int e = i >> 6, k = i & 63;
        W2t[e * 64 + k] = W2tmp[k * 148 + e];
    }
    __syncthreads();

    // ---- Stage B: FFMA2, warp-uniform g = w, px in {lane, lane+32} ----
    const int g = w;
    ull  acc[2][4];
    float acc8[2];
    {
        const float* bb = b2 + g * 9;
        ull b01 = pack2(bb[0], bb[1]), b23 = pack2(bb[2], bb[3]);
        ull b45 = pack2(bb[4], bb[5]), b67 = pack2(bb[6], bb[7]);
        float b8 = bb[8];
        #pragma unroll
        for (int pi = 0; pi < 2; pi++) {
            acc[pi][0] = b01; acc[pi][1] = b23; acc[pi][2] = b45; acc[pi][3] = b67;
            acc8[pi] = b8;
        }
    }
    {
        const float* t0r = &ts[lane * 68];
        const float* t1r = &ts[(lane + 32) * 68];
        const float* wb  = &W2t[g * 9 * 64];
        for (int k = 0; k < 64; k += 4) {
            float4 t0 = *(const float4*)&t0r[k];
            float4 t1 = *(const float4*)&t1r[k];
            float4 wv[9];
            #pragma unroll
            for (int j = 0; j < 9; j++) wv[j] = *(const float4*)&wb[j * 64 + k];  // uniform
            #pragma unroll
            for (int kk = 0; kk < 4; kk++) {
                ull W01 = pack2((&wv[0].x)[kk], (&wv[1].x)[kk]);
                ull W23 = pack2((&wv[2].x)[kk], (&wv[3].x)[kk]);
                ull W45 = pack2((&wv[4].x)[kk], (&wv[5].x)[kk]);
                ull W67 = pack2((&wv[6].x)[kk], (&wv[7].x)[kk]);
                float w8v = (&wv[8].x)[kk];
                float a0 = (&t0.x)[kk];
                ull A0 = pack2(a0, a0);
                ffma2(acc[0][0], A0, W01); ffma2(acc[0][1], A0, W23);
                ffma2(acc[0][2], A0, W45); ffma2(acc[0][3], A0, W67);
                acc8[0] = fmaf(a0, w8v, acc8[0]);
                float a1 = (&t1.x)[kk];
                ull A1 = pack2(a1, a1);
                ffma2(acc[1][0], A1, W01); ffma2(acc[1][1], A1, W23);
                ffma2(acc[1][2], A1, W45); ffma2(acc[1][3], A1, W67);
                acc8[1] = fmaf(a1, w8v, acc8[1]);
            }
        }
    }
    #pragma unroll
    for (int pi = 0; pi < 2; pi++) {
        const int px = lane + 32 * pi;
        float wr[9];
        unpack2(acc[pi][0], wr[0], wr[1]); unpack2(acc[pi][1], wr[2], wr[3]);
        unpack2(acc[pi][2], wr[4], wr[5]); unpack2(acc[pi][3], wr[6], wr[7]);
        wr[8] = acc8[pi];
        float* dst = g_wgt + ((size_t)g * NPIX + pix0 + px) * 9;
        #pragma unroll
        for (int j = 0; j < 9; j++) dst[j] = wr[j];
    }
}

// =====================================================================
// K2: involution. 512 threads (16 warps, g = warp), 8x8 tile, smem = halo
// only (104KB) -> 2 blocks/SM = 32 warps/SM.
// =====================================================================
#define XS 260
#define K2_SM_FLOATS (100 * XS)   // 104000 B

__global__ void __launch_bounds__(512, 2) invo_kernel(
    const float* __restrict__ x, float* __restrict__ out)
{
    extern __shared__ float sm[];
    float* xs = sm;                  // [100][XS]

    const int tid = threadIdx.x;
    const int blk = blockIdx.x;
    const int b  = blk >> 6;
    const int ty = (blk >> 3) & 7;
    const int tw = blk & 7;
    const int h0 = ty * 8, w0 = tw * 8;

    const int lane = tid & 31, g = tid >> 5;   // one group per warp
    const int py0 = lane >> 3, pxx = lane & 7;

    // ---- wgt loads (gmem) issued before the smem fill ----
    float wr[2][9];
    #pragma unroll
    for (int pi = 0; pi < 2; pi++) {
        const int py = py0 + 4 * pi;
        const int gpix = (b * 64 + h0 + py) * 64 + w0 + pxx;
        const float* src = g_wgt + ((size_t)g * NPIX + gpix) * 9;
        #pragma unroll
        for (int j = 0; j < 9; j++) wr[pi][j] = src[j];
    }

    // ---- halo load: 100 pixel slots x 64 float4, zero-pad OOB ----
    for (int i = tid; i < 6400; i += 512) {
        int slot = i >> 6, c4 = i & 63;
        int py = slot / 10, px = slot - py * 10;
        int gh = h0 + py - 1, gw = w0 + px - 1;
        float4 v = make_float4(0.f, 0.f, 0.f, 0.f);
        if ((unsigned)gh < 64u && (unsigned)gw < 64u)
            v = *(const float4*)(x + ((size_t)((b * 64 + gh) * 64 + gw)) * 256 + c4 * 4);
        *(float4*)&xs[slot * XS + c4 * 4] = v;
    }
    __syncthreads();

    // ---- involution ----
    const int base0 = (py0 * 10 + pxx) * XS;      // window top-left slot
    float* orow0 = out + ((size_t)((b * 64 + h0 + py0) * 64 + w0 + pxx)) * 256 + g * 16;
    float* orow1 = orow0 + (size_t)4 * 64 * 256;

    #pragma unroll
    for (int gcc = 0; gcc < 4; gcc++) {
        float o0[4] = {0.f, 0.f, 0.f, 0.f};
        float o1[4] = {0.f, 0.f, 0.f, 0.f};
        #pragma unroll
        for (int u = 0; u < 9; u++) {
            int f  = g * 144 + gcc * 36 + 4 * u;
            int n  = f >> 8;              // neighbor, constant across the float4
            int ch = f & 255;
            int ni = n / 3, nj = n - ni * 3;
            int off = (ni * 10 + nj) * XS + ch;
            float4 v0 = *(const float4*)&xs[base0 + off];
            float4 v1 = *(const float4*)&xs[base0 + 40 * XS + off];
            const int i0 = 4 * u;
            o0[(i0 + 0) / 9] = fmaf(wr[0][(i0 + 0) % 9], v0.x, o0[(i0 + 0) / 9]);
            o0[(i0 + 1) / 9] = fmaf(wr[0][(i0 + 1) % 9], v0.y, o0[(i0 + 1) / 9]);
            o0[(i0 + 2) / 9] = fmaf(wr[0][(i0 + 2) % 9], v0.z, o0[(i0 + 2) / 9]);
            o0[(i0 + 3) / 9] = fmaf(wr[0][(i0 + 3) % 9], v0.w, o0[(i0 + 3) / 9]);
            o1[(i0 + 0) / 9] = fmaf(wr[1][(i0 + 0) % 9], v1.x, o1[(i0 + 0) / 9]);
            o1[(i0 + 1) / 9] = fmaf(wr[1][(i0 + 1) % 9], v1.y, o1[(i0 + 1) / 9]);
            o1[(i0 + 2) / 9] = fmaf(wr[1][(i0 + 2) % 9], v1.z, o1[(i0 + 2) / 9]);
            o1[(i0 + 3) / 9] = fmaf(wr[1][(i0 + 3) % 9], v1.w, o1[(i0 + 3) / 9]);
        }
        *(float4*)&orow0[gcc * 4] = make_float4(o0[0], o0[1], o0[2], o0[3]);
        *(float4*)&orow1[gcc * 4] = make_float4(o1[0], o1[1], o1[2], o1[3]);
    }
}

extern "C" void kernel_launch(void* const* d_in, const int* in_sizes, int n_in,
                              void* d_out, int out_size) {
    const float* x  = (const float*)d_in[0];
    const float* W1 = (const float*)d_in[1];
    const float* b1 = (const float*)d_in[2];
    const float* W2 = (const float*)d_in[3];
    const float* b2 = (const float*)d_in[4];
    float* out = (float*)d_out;

    const int SM1 = K1_SM_FLOATS * 4;   // 214016 B
    const int SM2 = K2_SM_FLOATS * 4;   // 104000 B
    cudaFuncSetAttribute(wgt_kernel,  cudaFuncAttributeMaxDynamicSharedMemorySize, SM1);
    cudaFuncSetAttribute(invo_kernel, cudaFuncAttributeMaxDynamicSharedMemorySize, SM2);

    wgt_kernel<<<512, 512, SM1>>>(x, W1, b1, W2, b2);
    invo_kernel<<<512, 512, SM2>>>(x, out);
}

// round 11
// speedup vs baseline: 1.5422x; 1.2601x over previous
#include <cuda_runtime.h>
#include <cstdint>

// Fixed shapes: B=8, H=W=64, C=256, red=64, G=16, GC=16, kk=9, E=144, NPIX=32768
#define NPIX 32768

// wgt scratch in [g][pix][9] layout: 16*32768*9 floats = 18.9MB
__device__ float g_wgt[(size_t)16 * NPIX * 9];

typedef unsigned long long ull;

__device__ __forceinline__ ull pack2(float lo, float hi) {
    ull r; asm("mov.b64 %0, {%1, %2};" : "=l"(r) : "f"(lo), "f"(hi)); return r;
}
__device__ __forceinline__ void unpack2(ull v, float& lo, float& hi) {
    asm("mov.b64 {%0, %1}, %2;" : "=f"(lo), "=f"(hi) : "l"(v));
}
__device__ __forceinline__ void ffma2(ull& d, ull a, ull b) {
    asm("fma.rn.f32x2 %0, %1, %2, %0;" : "+l"(d) : "l"(a), "l"(b));
}
// pack two f32 into bf16x2: LOW half = f_even (lower k index), HIGH half = f_odd
__device__ __forceinline__ unsigned bfpack(float f_even, float f_odd) {
    unsigned r; asm("cvt.rn.bf16x2.f32 %0, %1, %2;" : "=r"(r) : "f"(f_odd), "f"(f_even)); return r;
}
__device__ __forceinline__ float bflo(unsigned u) { return __uint_as_float(u << 16); }
__device__ __forceinline__ float bfhi(unsigned u) { return __uint_as_float(u & 0xffff0000u); }

__device__ __forceinline__ void mma_bf16(float* c, const unsigned* a, unsigned b0, unsigned b1) {
    asm("mma.sync.aligned.m16n8k16.row.col.f32.bf16.bf16.f32 "
        "{%0,%1,%2,%3}, {%4,%5,%6,%7}, {%8,%9}, {%0,%1,%2,%3};"
        : "+f"(c[0]), "+f"(c[1]), "+f"(c[2]), "+f"(c[3])
        : "r"(a[0]), "r"(a[1]), "r"(a[2]), "r"(a[3]), "r"(b0), "r"(b1));
}

// =====================================================================
// K1: g_wgt = ((x @ W1 + b1) @ W2 + b2). 512 threads, 64 pixels, grid 512.
// Stage A: bf16 m16n8k16, 3-term hi/lo split, K processed in 2 chunks of 128
// so the per-chunk hi/lo operand buffers stay small -> 2 blocks/SM.
// smem (32-bit words), total 23040 words = 92160 B:
//   chunk phase:   xhi[64][68] @0 | xlo[64][68] @4352 | w1hi[64][72] @8704 | w1lo[64][72] @13312
//   overlay phase: ts[64][68] @0  | W2tmp[64][148] @4352 | W2t[144][64] @13824
// =====================================================================
#define K1_SM_WORDS 23040

__global__ void __launch_bounds__(512, 2) wgt_kernel(
    const float* __restrict__ x,
    const float* __restrict__ W1, const float* __restrict__ b1,
    const float* __restrict__ W2, const float* __restrict__ b2)
{
    extern __shared__ float sm[];
    unsigned* xhi  = (unsigned*)sm;            // [64][68]  (64 k-pairs of this chunk)
    unsigned* xlo  = xhi + 4352;               // [64][68]
    unsigned* w1hi = xlo + 4352;               // [64][72]
    unsigned* w1lo = w1hi + 4608;              // [64][72]
    float*    ts    = sm;                      // overlay [64][68]
    float*    W2tmp = sm + 4352;               // overlay [64][148]
    float*    W2t   = sm + 13824;              // overlay [144][64]

    const int tid  = threadIdx.x;
    const int pix0 = blockIdx.x * 64;

    const int w = tid >> 5, lane = tid & 31;
    const int quad = lane >> 2, tq = lane & 3;
    const int mw = w & 3, nw = w >> 2;

    float cfr[2][4];
    #pragma unroll
    for (int nt = 0; nt < 2; nt++)
        #pragma unroll
        for (int j = 0; j < 4; j++) cfr[nt][j] = 0.f;

    // ---- Stage A over 2 K-chunks of 128 channels ----
    for (int chunk = 0; chunk < 2; chunk++) {
        // convert x[:, chunk*128 : +128] -> bf16x2 hi/lo k-pairs (local pair idx 0..63)
        for (int j = tid; j < 2048; j += 512) {
            int r = j >> 5, c4 = j & 31;
            float4 v = *(const float4*)(x + (size_t)(pix0 + r) * 256 + chunk * 128 + c4 * 4);
            unsigned h0 = bfpack(v.x, v.y);
            unsigned l0 = bfpack(v.x - bflo(h0), v.y - bfhi(h0));
            unsigned h1 = bfpack(v.z, v.w);
            unsigned l1 = bfpack(v.z - bflo(h1), v.w - bfhi(h1));
            int base = r * 68 + 2 * c4;
            xhi[base] = h0; xhi[base + 1] = h1;
            xlo[base] = l0; xlo[base + 1] = l1;
        }
        // convert W1[chunk*128 : +128][:] -> hi/lo k-pairs w1hi[kp_local][col]
        for (int j = tid; j < 4096; j += 512) {
            int kpl = j >> 6, c = j & 63;
            int krow = chunk * 128 + 2 * kpl;
            float f0 = W1[(size_t)krow * 64 + c];
            float f1 = W1[(size_t)(krow + 1) * 64 + c];
            unsigned h = bfpack(f0, f1);
            unsigned l = bfpack(f0 - bflo(h), f1 - bfhi(h));
            w1hi[kpl * 72 + c] = h;
            w1lo[kpl * 72 + c] = l;
        }
        __syncthreads();

        // mma: 16 warps = 4m x 4n; warp = m16 tile x 2 n8 tiles; 8 k16-steps
        {
            const int r0 = mw * 16 + quad;
            const unsigned* xh0 = &xhi[r0 * 68];
            const unsigned* xh8 = &xhi[(r0 + 8) * 68];
            const unsigned* xl0 = &xlo[r0 * 68];
            const unsigned* xl8 = &xlo[(r0 + 8) * 68];
            #pragma unroll
            for (int ks = 0; ks < 8; ks++) {
                const int kp = 8 * ks + tq;          // local pair 0..63
                unsigned ah[4], al[4];
                ah[0] = xh0[kp];     ah[1] = xh8[kp];
                ah[2] = xh0[kp + 4]; ah[3] = xh8[kp + 4];
                al[0] = xl0[kp];     al[1] = xl8[kp];
                al[2] = xl0[kp + 4]; al[3] = xl8[kp + 4];
                #pragma unroll
                for (int nt = 0; nt < 2; nt++) {
                    const int n0 = nw * 16 + nt * 8 + quad;
                    unsigned b0h = w1hi[kp * 72 + n0];
                    unsigned b1h = w1hi[(kp + 4) * 72 + n0];
                    unsigned b0l = w1lo[kp * 72 + n0];
                    unsigned b1l = w1lo[(kp + 4) * 72 + n0];
                    mma_bf16(cfr[nt], ah, b0h, b1h);   // hi*hi
                    mma_bf16(cfr[nt], ah, b0l, b1l);   // hi*lo
                    mma_bf16(cfr[nt], al, b0h, b1h);   // lo*hi
                }
            }
        }
        __syncthreads();   // buffers reusable (next chunk / overlays)
    }

    // ---- write ts (+b1); load W2 raw ----
    {
        const int r0 = mw * 16 + quad;
        #pragma unroll
        for (int nt = 0; nt < 2; nt++) {
            const int nb = nw * 16 + nt * 8 + 2 * tq;
            float bia0 = b1[nb], bia1 = b1[nb + 1];
            ts[r0 * 68 + nb]           = cfr[nt][0] + bia0;
            ts[r0 * 68 + nb + 1]       = cfr[nt][1] + bia1;
            ts[(r0 + 8) * 68 + nb]     = cfr[nt][2] + bia0;
            ts[(r0 + 8) * 68 + nb + 1] = cfr[nt][3] + bia1;
        }
    }
    {
        const float4* src = (const float4*)W2;
        for (int i = tid; i < 2304; i += 512) {
            int r = i / 36, c4 = i - r * 36;
            *(float4*)&W2tmp[r * 148 + c4 * 4] = src[i];
        }
    }
    __syncthreads();

    // ---- transpose W2tmp[k][e] -> W2t[e][k] ----
    for (int i = tid; i < 9216; i += 512) {
        int e = i >> 6, k = i & 63;
        W2t[e * 64 + k] = W2tmp[k * 148 + e];
    }
    __syncthreads();

    // ---- Stage B: FFMA2, warp-uniform g = w, px in {lane, lane+32} ----
    const int g = w;
    ull  acc[2][4];
    float acc8[2];
    {
        const float* bb = b2 + g * 9;
        ull b01 = pack2(bb[0], bb[1]), b23 = pack2(bb[2], bb[3]);
        ull b45 = pack2(bb[4], bb[5]), b67 = pack2(bb[6], bb[7]);
        float b8 = bb[8];
        #pragma unroll
        for (int pi = 0; pi < 2; pi++) {
            acc[pi][0] = b01; acc[pi][1] = b23; acc[pi][2] = b45; acc[pi][3] = b67;
            acc8[pi] = b8;
        }
    }
    {
        const float* t0r = &ts[lane * 68];
        const float* t1r = &ts[(lane + 32) * 68];
        const float* wb  = &W2t[g * 9 * 64];
        for (int k = 0; k < 64; k += 4) {
            float4 t0 = *(const float4*)&t0r[k];
            float4 t1 = *(const float4*)&t1r[k];
            {
                float4 w8 = *(const float4*)&wb[8 * 64 + k];   // uniform
                #pragma unroll
                for (int kk = 0; kk < 4; kk++) {
                    acc8[0] = fmaf((&t0.x)[kk], (&w8.x)[kk], acc8[0]);
                    acc8[1] = fmaf((&t1.x)[kk], (&w8.x)[kk], acc8[1]);
                }
            }
            #pragma unroll
            for (int jp = 0; jp < 4; jp++) {
                float4 wa = *(const float4*)&wb[(2 * jp) * 64 + k];       // uniform
                float4 wc = *(const float4*)&wb[(2 * jp + 1) * 64 + k];   // uniform
                #pragma unroll
                for (int kk = 0; kk < 4; kk++) {
                    ull W = pack2((&wa.x)[kk], (&wc.x)[kk]);
                    float a0 = (&t0.x)[kk];
                    float a1 = (&t1.x)[kk];
                    ffma2(acc[0][jp], pack2(a0, a0), W);
                    ffma2(acc[1][jp], pack2(a1, a1), W);
                }
            }
        }
    }
    #pragma unroll
    for (int pi = 0; pi < 2; pi++) {
        const int px = lane + 32 * pi;
        float wr[9];
        unpack2(acc[pi][0], wr[0], wr[1]); unpack2(acc[pi][1], wr[2], wr[3]);
        unpack2(acc[pi][2], wr[4], wr[5]); unpack2(acc[pi][3], wr[6], wr[7]);
        wr[8] = acc8[pi];
        float* dst = g_wgt + ((size_t)g * NPIX + pix0 + px) * 9;
        #pragma unroll
        for (int j = 0; j < 9; j++) dst[j] = wr[j];
    }
}

// =====================================================================
// K2: involution. 512 threads (g = warp), 8x8 tile, smem = halo only
// (104KB) -> 2 blocks/SM.
// =====================================================================
#define XS 260
#define K2_SM_FLOATS (100 * XS)   // 104000 B

__global__ void __launch_bounds__(512, 2) invo_kernel(
    const float* __restrict__ x, float* __restrict__ out)
{
    extern __shared__ float sm[];
    float* xs = sm;                  // [100][XS]

    const int tid = threadIdx.x;
    const int blk = blockIdx.x;
    const int b  = blk >> 6;
    const int ty = (blk >> 3) & 7;
    const int tw = blk & 7;
    const int h0 = ty * 8, w0 = tw * 8;

    const int lane = tid & 31, g = tid >> 5;
    const int py0 = lane >> 3, pxx = lane & 7;

    // ---- wgt loads (gmem) issued before the smem fill ----
    float wr[2][9];
    #pragma unroll
    for (int pi = 0; pi < 2; pi++) {
        const int py = py0 + 4 * pi;
        const int gpix = (b * 64 + h0 + py) * 64 + w0 + pxx;
        const float* src = g_wgt + ((size_t)g * NPIX + gpix) * 9;
        #pragma unroll
        for (int j = 0; j < 9; j++) wr[pi][j] = src[j];
    }

    // ---- halo load: 100 pixel slots x 64 float4, zero-pad OOB ----
    for (int i = tid; i < 6400; i += 512) {
        int slot = i >> 6, c4 = i & 63;
        int py = slot / 10, px = slot - py * 10;
        int gh = h0 + py - 1, gw = w0 + px - 1;
        float4 v = make_float4(0.f, 0.f, 0.f, 0.f);
        if ((unsigned)gh < 64u && (unsigned)gw < 64u)
            v = *(const float4*)(x + ((size_t)((b * 64 + gh) * 64 + gw)) * 256 + c4 * 4);
        *(float4*)&xs[slot * XS + c4 * 4] = v;
    }
    __syncthreads();

    // ---- involution ----
    const int base0 = (py0 * 10 + pxx) * XS;      // window top-left slot
    float* orow0 = out + ((size_t)((b * 64 + h0 + py0) * 64 + w0 + pxx)) * 256 + g * 16;
    float* orow1 = orow0 + (size_t)4 * 64 * 256;

    #pragma unroll
    for (int gcc = 0; gcc < 4; gcc++) {
        float o0[4] = {0.f, 0.f, 0.f, 0.f};
        float o1[4] = {0.f, 0.f, 0.f, 0.f};
        #pragma unroll
        for (int u = 0; u < 9; u++) {
            int f  = g * 144 + gcc * 36 + 4 * u;
            int n  = f >> 8;              // neighbor, constant across the float4
            int ch = f & 255;
            int ni = n / 3, nj = n - ni * 3;
            int off = (ni * 10 + nj) * XS + ch;
            float4 v0 = *(const float4*)&xs[base0 + off];
            float4 v1 = *(const float4*)&xs[base0 + 40 * XS + off];
            const int i0 = 4 * u;
            o0[(i0 + 0) / 9] = fmaf(wr[0][(i0 + 0) % 9], v0.x, o0[(i0 + 0) / 9]);
            o0[(i0 + 1) / 9] = fmaf(wr[0][(i0 + 1) % 9], v0.y, o0[(i0 + 1) / 9]);
            o0[(i0 + 2) / 9] = fmaf(wr[0][(i0 + 2) % 9], v0.z, o0[(i0 + 2) / 9]);
            o0[(i0 + 3) / 9] = fmaf(wr[0][(i0 + 3) % 9], v0.w, o0[(i0 + 3) / 9]);
            o1[(i0 + 0) / 9] = fmaf(wr[1][(i0 + 0) % 9], v1.x, o1[(i0 + 0) / 9]);
            o1[(i0 + 1) / 9] = fmaf(wr[1][(i0 + 1) % 9], v1.y, o1[(i0 + 1) / 9]);
            o1[(i0 + 2) / 9] = fmaf(wr[1][(i0 + 2) % 9], v1.z, o1[(i0 + 2) / 9]);
            o1[(i0 + 3) / 9] = fmaf(wr[1][(i0 + 3) % 9], v1.w, o1[(i0 + 3) / 9]);
        }
        *(float4*)&orow0[gcc * 4] = make_float4(o0[0], o0[1], o0[2], o0[3]);
        *(float4*)&orow1[gcc * 4] = make_float4(o1[0], o1[1], o1[2], o1[3]);
    }
}

extern "C" void kernel_launch(void* const* d_in, const int* in_sizes, int n_in,
                              void* d_out, int out_size) {
    const float* x  = (const float*)d_in[0];
    const float* W1 = (const float*)d_in[1];
    const float* b1 = (const float*)d_in[2];
    const float* W2 = (const float*)d_in[3];
    const float* b2 = (const float*)d_in[4];
    float* out = (float*)d_out;

    const int SM1 = K1_SM_WORDS * 4;    // 92160 B
    const int SM2 = K2_SM_FLOATS * 4;   // 104000 B
    cudaFuncSetAttribute(wgt_kernel,  cudaFuncAttributeMaxDynamicSharedMemorySize, SM1);
    cudaFuncSetAttribute(invo_kernel, cudaFuncAttributeMaxDynamicSharedMemorySize, SM2);

    wgt_kernel<<<512, 512, SM1>>>(x, W1, b1, W2, b2);
    invo_kernel<<<512, 512, SM2>>>(x, out);
}